// round 12
// baseline (speedup 1.0000x reference)
#include <cuda_runtime.h>
#include <cstddef>

typedef unsigned long long u64;

__device__ __forceinline__ u64 pk2(float lo, float hi) {
    u64 r; asm("mov.b64 %0,{%1,%2};" : "=l"(r) : "f"(lo), "f"(hi)); return r;
}
__device__ __forceinline__ void upk2(u64 v, float& lo, float& hi) {
    asm("mov.b64 {%0,%1},%2;" : "=f"(lo), "=f"(hi) : "l"(v));
}
__device__ __forceinline__ void fma2(u64& d, u64 a, u64 b) {
    asm("fma.rn.f32x2 %0,%1,%2,%0;" : "+l"(d) : "l"(a), "l"(b));
}
__device__ __forceinline__ u64 add2(u64 a, u64 b) {
    u64 r; asm("add.rn.f32x2 %0,%1,%2;" : "=l"(r) : "l"(a), "l"(b)); return r;
}

// B=256, L=64, D=1024
// left'[k,d] = sum_l Wl[k,l]*left[l,d] + bl[k]   (same right)
// corr[i,d]  = sum_j left'[j,d]*right'[j+63-i,d] (i in [0,128), row 127 = 0)
// y[k,d]     = sum_c sum_t Wconv[k,c,t]*corr[c,d+t-1]  (zero pad in d)

namespace {
constexpr int Dc  = 1024;
constexpr int SAB = 66;                           // A/B row stride; col c at offset c
constexpr int SCr = 68;                           // corr / W^T row stride
constexpr int OFF_A = 0;                          // 64 rows  left'
constexpr int OFF_B = 64 * SAB;                   // 192 rows: pads + right' rows 64..127
constexpr int OFF_C = OFF_B + 192 * SAB;          // 128 rows corr; aliased: W^T / partials
constexpr int WT_SZ = 64 * SCr;                   // 4352/mat
constexpr int SMEM_FLOATS = OFF_C + 128 * SCr;    // 25600 fl = 102400 B -> 2 CTAs/SM
constexpr int SMEM_BYTES  = SMEM_FLOATS * 4;
constexpr int U64_B  = OFF_B / 2;                 // u64 index of B region (2112)
constexpr int U64_C  = OFF_C / 2;                 // u64 index of corr (8448)
constexpr int WA_U2  = U64_B / 2;                 // ulonglong2 index of wA (1056)
constexpr int WB_U64 = U64_B + 32 * 65 * 2;       // u64 index of wB (6272; end 8352)
}

__global__ void __launch_bounds__(256, 2)
cc_fused_kernel(const float* __restrict__ left,  const float* __restrict__ right,
                const float* __restrict__ Wl,    const float* __restrict__ bl,
                const float* __restrict__ Wr,    const float* __restrict__ br,
                const float* __restrict__ Wconv, float* __restrict__ out)
{
    extern __shared__ float sm[];
    const int tid = threadIdx.x;
    const int b   = blockIdx.y;
    const int dg0 = blockIdx.x * 64;    // global d of tile col 1 (col 0 = d-1 halo)

    // ---- phase 0: raws into pad rows (B_raw rows 0..63, A_raw rows 128..191), W^T ----
    const float* Lb = left  + (size_t)b * 65536;
    const float* Rb = right + (size_t)b * 65536;
    for (int i = tid; i < 64 * 66; i += 256) {
        int r = i / 66, c = i % 66;
        int d = dg0 + c - 1;
        float lv = 0.f, rv = 0.f;
        if ((unsigned)d < (unsigned)Dc) { lv = Lb[r * Dc + d]; rv = Rb[r * Dc + d]; }
        sm[OFF_B + (128 + r) * SAB + c] = lv;    // A_raw
        sm[OFF_B + r * SAB + c]         = rv;    // B_raw
    }
    for (int i = tid; i < 8192; i += 256) {      // W^T[l][k], stride 68, in corr region
        int which = i >> 12, r = i & 4095;
        int k = r >> 6, l = r & 63;
        sm[OFF_C + which * WT_SZ + l * SCr + k] = (which ? Wr : Wl)[r];
    }
    __syncthreads();

    // ---- phase 1: linears, out-of-place, unique weight stream per warp ----
    {
        const int w    = tid >> 5, lane = tid & 31;
        const int mat  = w >> 2;                 // 0: left, 1: right
        const int kq   = w & 3,  k0 = kq * 16;
        const u64* rawp = reinterpret_cast<const u64*>(sm) + U64_B
                          + (mat ? 0 : 128 * 33) + lane;
        const ulonglong2* wt2 = reinterpret_cast<const ulonglong2*>(sm + OFF_C + mat * WT_SZ);
        const float* bias = mat ? br : bl;

        u64 acc[8][2];
        #pragma unroll
        for (int kp = 0; kp < 8; ++kp) {
            u64 bp_ = pk2(__ldg(bias + k0 + 2 * kp), __ldg(bias + k0 + 2 * kp + 1));
            acc[kp][0] = bp_; acc[kp][1] = bp_;
        }
        #pragma unroll 4
        for (int l = 0; l < 64; ++l) {
            u64 rp = rawp[l * 33];               // cols (2*lane, 2*lane+1)
            float c0, c1; upk2(rp, c0, c1);
            u64 p0 = pk2(c0, c0), p1 = pk2(c1, c1);
            const ulonglong2* wl_ = wt2 + l * 17 + 4 * kq;
            #pragma unroll
            for (int i = 0; i < 4; ++i) {
                ulonglong2 ww = wl_[i];          // k-pairs (2i, 2i+1)
                fma2(acc[2 * i][0],     ww.x, p0);
                fma2(acc[2 * i][1],     ww.x, p1);
                fma2(acc[2 * i + 1][0], ww.y, p0);
                fma2(acc[2 * i + 1][1], ww.y, p1);
            }
        }
        u64* ost = reinterpret_cast<u64*>(sm) + (mat ? (OFF_B + 64 * SAB) / 2 : 0) + lane;
        #pragma unroll
        for (int kp = 0; kp < 8; ++kp) {
            float a0, b0_, a1, b1_;
            upk2(acc[kp][0], a0, b0_);
            upk2(acc[kp][1], a1, b1_);
            ost[(k0 + 2 * kp) * 33]     = pk2(a0, a1);
            ost[(k0 + 2 * kp + 1) * 33] = pk2(b0_, b1_);
        }

        // tail cols (64,65) as u64 pair: 2 mats x 64 k x 2 l-halves = 256 items
        const int hmat = tid >> 7;
        const int hk   = (tid >> 1) & 63;
        const int lh   = tid & 1;
        const u64* rawt = reinterpret_cast<const u64*>(sm) + U64_B
                          + (hmat ? 0 : 128 * 33) + 32;
        const float* wt = sm + OFF_C + hmat * WT_SZ + hk;
        u64 hacc = lh ? 0ull
                      : pk2(__ldg((hmat ? br : bl) + hk), __ldg((hmat ? br : bl) + hk));
        #pragma unroll 8
        for (int t = 0; t < 32; ++t) {
            int l = 32 * lh + t;
            float wv = wt[l * SCr];
            fma2(hacc, pk2(wv, wv), rawt[l * 33]);
        }
        float alo, ahi; upk2(hacc, alo, ahi);
        alo += __shfl_xor_sync(0xFFFFFFFFu, alo, 1);
        ahi += __shfl_xor_sync(0xFFFFFFFFu, ahi, 1);
        if (!lh)
            reinterpret_cast<u64*>(sm)[(hmat ? (OFF_B + 64 * SAB) / 2 : 0) + hk * 33 + 32]
                = pk2(alo, ahi);
    }
    __syncthreads();

    // ---- interlude: zero pad rows used by phase 2 ----
    {
        u64* zb = reinterpret_cast<u64*>(sm) + U64_B;
        for (int i = tid; i < 528; i += 256) {   // full rows 56..63, 128..135
            int r = i / 33, c = i % 33;
            int row = (r < 8) ? (56 + r) : (120 + r);
            zb[row * 33 + c] = 0ull;
        }
        for (int i = tid; i < 112; i += 256) {   // halo word of pad rows 0..55, 136..191
            int row = (i < 56) ? i : (80 + i);
            zb[row * 33 + 32] = 0ull;
        }
    }
    __syncthreads();

    // ---- phase 2: correlation, triangular paired blocks ----
    {
        const int cp = tid & 31;                  // col pair (2cp, 2cp+1)
        const int ig = tid >> 5;                  // 0..7
        const u64* ap = reinterpret_cast<const u64*>(sm + OFF_A) + cp;   // row stride 33
        const u64* bp = reinterpret_cast<const u64*>(sm + OFF_B) + cp;
        u64* cst = reinterpret_cast<u64*>(sm + OFF_C) + cp;              // row stride 34
        const u64 keep = (dg0 == 0 && cp == 0) ? 0xFFFFFFFF00000000ull : ~0ull;

        #pragma unroll 1
        for (int blk = 0; blk < 2; ++blk) {
            const int i0  = blk ? (64 + 8 * ig) : (8 * ig);
            const int jlo = blk ? (8 * ig) : 0;
            const int nch = blk ? (8 - ig) : (ig + 1);
            u64 acc[8], win[8];
            #pragma unroll
            for (int q = 0; q < 8; ++q) acc[q] = 0ull;
            #pragma unroll
            for (int q = 1; q < 8; ++q) win[q] = bp[(jlo + 127 - i0 - q) * 33];
            #pragma unroll 1
            for (int ch = 0; ch < nch; ++ch) {
                const int j0 = jlo + ch * 8;
                u64 a2[8];
                #pragma unroll
                for (int t = 0; t < 8; ++t) a2[t] = ap[(j0 + t) * 33];
                #pragma unroll
                for (int t = 0; t < 8; ++t) {
                    u64 nv = bp[(j0 + t + 127 - i0) * 33];
                    fma2(acc[0], a2[t], nv);
                    #pragma unroll
                    for (int q = 1; q < 8; ++q) fma2(acc[q], a2[t], win[q]);
                    #pragma unroll
                    for (int q = 7; q > 1; --q) win[q] = win[q - 1];
                    win[1] = nv;
                }
            }
            #pragma unroll
            for (int q = 0; q < 8; ++q) cst[(i0 + q) * 34] = acc[q] & keep;
        }

        // tail cols (64,65) u64 pairs, split j-range: 128 i x 2 j-halves
        const int hi = tid >> 1;
        const int jh = tid & 1;
        const u64* a2p = reinterpret_cast<const u64*>(sm) + 32;          // A row j halo word
        const u64* b2p = reinterpret_cast<const u64*>(sm) + U64_B + 32;  // B row halo word
        u64 hacc = 0ull;
        #pragma unroll 8
        for (int t = 0; t < 32; ++t) {
            int j = 32 * jh + t;
            fma2(hacc, a2p[j * 33], b2p[(j + 127 - hi) * 33]);
        }
        float alo, ahi; upk2(hacc, alo, ahi);
        alo += __shfl_xor_sync(0xFFFFFFFFu, alo, 1);
        ahi += __shfl_xor_sync(0xFFFFFFFFu, ahi, 1);
        if (!jh) {
            u64 v = pk2(alo, ahi);
            if (dg0 == 960) v &= 0x00000000FFFFFFFFull;   // col 65 = d 1024 invalid
            reinterpret_cast<u64*>(sm)[U64_C + hi * 34 + 32] = v;
        }
    }

    // ---- phase 3: conv(128->64,k=3), 8d x 4k per thread, c-split groups ----
    const int chalf = tid >> 7;                   // c-quarter owner
    const int r3  = tid & 127;
    const int kq3 = r3 >> 3;                      // 0..15 -> k rows 4kq3..4kq3+3
    const int dq3 = r3 & 7;                       // d0 = 8*dq3
    const int d0  = 8 * dq3;
    u64 acc[2][8];
    #pragma unroll
    for (int p = 0; p < 2; ++p)
        #pragma unroll
        for (int dd = 0; dd < 8; ++dd) acc[p][dd] = 0ull;

    #pragma unroll 1
    for (int half = 0; half < 2; ++half) {
        __syncthreads();   // corr written / prev weight & B reads done before restage
        for (int i = tid; i < 2048; i += 256) {
            int kp = i >> 6, cl = i & 63;
            const float* s0 = Wconv + (2 * kp) * 384 + half * 192 + cl * 3;
            ulonglong2 v;
            v.x = pk2(__ldg(s0 + 0), __ldg(s0 + 384));
            v.y = pk2(__ldg(s0 + 1), __ldg(s0 + 385));
            (reinterpret_cast<ulonglong2*>(sm) + WA_U2)[kp * 65 + cl] = v;
            (reinterpret_cast<u64*>(sm) + WB_U64)[kp * 65 + cl] =
                pk2(__ldg(s0 + 2), __ldg(s0 + 386));
        }
        __syncthreads();
        const ulonglong2* wA = reinterpret_cast<const ulonglong2*>(sm) + WA_U2;
        const u64*        wB = reinterpret_cast<const u64*>(sm) + WB_U64;
        const float* cbase = sm + OFF_C + (half * 64 + 32 * chalf) * SCr + d0;
        #pragma unroll 2
        for (int cl2 = 0; cl2 < 32; ++cl2) {
            const int clw = 32 * chalf + cl2;     // cl index within this half
            const float* crow = cbase + cl2 * SCr;
            ulonglong2 cA = *reinterpret_cast<const ulonglong2*>(crow);
            ulonglong2 cB = *reinterpret_cast<const ulonglong2*>(crow + 4);
            float2     cC = *reinterpret_cast<const float2*>(crow + 8);
            float f0, f1, f2, f3, f4, f5, f6, f7;
            upk2(cA.x, f0, f1); upk2(cA.y, f2, f3);
            upk2(cB.x, f4, f5); upk2(cB.y, f6, f7);
            u64 cv[10] = { pk2(f0, f0), pk2(f1, f1), pk2(f2, f2), pk2(f3, f3),
                           pk2(f4, f4), pk2(f5, f5), pk2(f6, f6), pk2(f7, f7),
                           pk2(cC.x, cC.x), pk2(cC.y, cC.y) };
            #pragma unroll
            for (int p = 0; p < 2; ++p) {
                const int kpg = 2 * kq3 + p;
                ulonglong2 wa = wA[kpg * 65 + clw];
                u64        wb = wB[kpg * 65 + clw];
                #pragma unroll
                for (int dd = 0; dd < 8; ++dd) {
                    fma2(acc[p][dd], wa.x, cv[dd]);
                    fma2(acc[p][dd], wa.y, cv[dd + 1]);
                    fma2(acc[p][dd], wb,   cv[dd + 2]);
                }
            }
        }
    }

    // ---- cross-group reduction (partials over corr region) + output ----
    __syncthreads();                              // all corr reads done
    u64* part = reinterpret_cast<u64*>(sm) + U64_C;
    if (chalf) {
        #pragma unroll
        for (int p = 0; p < 2; ++p)
            #pragma unroll
            for (int dd = 0; dd < 8; ++dd) part[r3 * 17 + p * 8 + dd] = acc[p][dd];
    }
    __syncthreads();
    if (!chalf) {
        float* ob = out + (size_t)b * 65536 + dg0 + d0;
        #pragma unroll
        for (int p = 0; p < 2; ++p) {
            float lo[8], hi[8];
            #pragma unroll
            for (int dd = 0; dd < 8; ++dd) {
                u64 s = add2(acc[p][dd], part[r3 * 17 + p * 8 + dd]);
                upk2(s, lo[dd], hi[dd]);
            }
            float* o0 = ob + (size_t)(4 * kq3 + 2 * p) * Dc;
            float* o1 = o0 + Dc;
            *reinterpret_cast<float4*>(o0)     = make_float4(lo[0], lo[1], lo[2], lo[3]);
            *reinterpret_cast<float4*>(o0 + 4) = make_float4(lo[4], lo[5], lo[6], lo[7]);
            *reinterpret_cast<float4*>(o1)     = make_float4(hi[0], hi[1], hi[2], hi[3]);
            *reinterpret_cast<float4*>(o1 + 4) = make_float4(hi[4], hi[5], hi[6], hi[7]);
        }
    }
}

extern "C" void kernel_launch(void* const* d_in, const int* in_sizes, int n_in,
                              void* d_out, int out_size)
{
    (void)in_sizes; (void)n_in; (void)out_size;
    const float* left  = (const float*)d_in[0];
    const float* right = (const float*)d_in[1];
    const float* Wl    = (const float*)d_in[2];
    const float* bl    = (const float*)d_in[3];
    const float* Wr    = (const float*)d_in[4];
    const float* br    = (const float*)d_in[5];
    const float* Wconv = (const float*)d_in[6];
    float* out = (float*)d_out;

    cudaFuncSetAttribute(cc_fused_kernel,
                         cudaFuncAttributeMaxDynamicSharedMemorySize, SMEM_BYTES);
    dim3 grid(Dc / 64, 256, 1);   // 4096 CTAs: one batch x 64-wide d-tile
    cc_fused_kernel<<<grid, 256, SMEM_BYTES>>>(left, right, Wl, bl, Wr, br, Wconv, out);
}

// round 13
// speedup vs baseline: 1.1190x; 1.1190x over previous
#include <cuda_runtime.h>
#include <cstddef>

typedef unsigned long long u64;

__device__ __forceinline__ u64 pk2(float lo, float hi) {
    u64 r; asm("mov.b64 %0,{%1,%2};" : "=l"(r) : "f"(lo), "f"(hi)); return r;
}
__device__ __forceinline__ void upk2(u64 v, float& lo, float& hi) {
    asm("mov.b64 {%0,%1},%2;" : "=f"(lo), "=f"(hi) : "l"(v));
}
__device__ __forceinline__ void fma2(u64& d, u64 a, u64 b) {
    asm("fma.rn.f32x2 %0,%1,%2,%0;" : "+l"(d) : "l"(a), "l"(b));
}

// B=256, L=64, D=1024
// left'[k,d] = sum_l Wl[k,l]*left[l,d] + bl[k]   (same right)
// corr[i,d]  = sum_j left'[j,d]*right'[j+63-i,d] (i in [0,128), row 127 = 0)
// y[k,d]     = sum_c sum_t Wconv[k,c,t]*corr[c,d+t-1]  (zero pad in d)

namespace {
constexpr int Dc  = 1024;
constexpr int ST  = 68;                          // row stride everywhere (17 u64-pairs)
constexpr int OFF_A = 0;                         // A = left': 64 rows, col c at offset c
constexpr int OFF_B = 64 * ST;                   // B: 79 local rows = orig rows 56..134
                                                 //   B' orig row r -> local r-56 (8..71)
constexpr int OFF_C = OFF_B + 79 * ST;           // 9724: W^T (ph0/1) -> corr 128 rows
constexpr int WT_SZ = 64 * ST;                   // 4352 per mat
constexpr int OFF_H = OFF_C + 128 * ST;          // 18428: halo raw scratch 128 u64
constexpr int SMEM_FLOATS = OFF_H + 256;         // 18684 fl = 74736 B -> 3 CTAs/SM
constexpr int SMEM_BYTES  = SMEM_FLOATS * 4;
constexpr int U64_B = OFF_B / 2;                 // 2176
constexpr int U64_C = OFF_C / 2;                 // 4862
constexpr int U64_H = OFF_H / 2;                 // 9214
}

__global__ void __launch_bounds__(256, 3)
cc_fused_kernel(const float* __restrict__ left,  const float* __restrict__ right,
                const float* __restrict__ Wl,    const float* __restrict__ bl,
                const float* __restrict__ Wr,    const float* __restrict__ br,
                const float* __restrict__ Wconv, float* __restrict__ out)
{
    extern __shared__ float sm[];
    const int tid = threadIdx.x;
    const int b   = blockIdx.y;
    const int dg0 = blockIdx.x * 64;    // global d of tile col 1 (col 0 = d-1 halo)
    const float* Lb = left  + (size_t)b * 65536;
    const float* Rb = right + (size_t)b * 65536;

    // ---- phase 0: W^T, halo raw scratch, zero B pad rows ----
    for (int i = tid; i < 8192; i += 256) {      // W^T[l][k], stride 68, in C region
        int which = i >> 12, r = i & 4095;
        int k = r >> 6, l = r & 63;
        sm[OFF_C + which * WT_SZ + l * ST + k] = (which ? Wr : Wl)[r];
    }
    if (tid < 128) {                             // H[mat*64+l] = {raw[l][dg0-1], raw[l][dg0+64]}
        int mat = tid >> 6, l = tid & 63;
        const float* src = (mat ? Rb : Lb) + l * 1024;
        float f0 = dg0 ? __ldg(src + dg0 - 1) : 0.f;
        float f1 = (dg0 != 960) ? __ldg(src + dg0 + 64) : 0.f;
        reinterpret_cast<u64*>(sm)[U64_H + tid] = pk2(f0, f1);
    }
    {
        u64* zb = reinterpret_cast<u64*>(sm) + U64_B;
        for (int i = tid; i < 510; i += 256) {   // pad rows local 0..7, 72..78
            int r = i / 34, c = i % 34;
            int row = (r < 8) ? r : (64 + r);
            zb[row * 34 + c] = 0ull;
        }
    }
    __syncthreads();

    // ---- phase 1: linears, raw streamed from global, outputs to smem ----
    {
        const int w    = tid >> 5, lane = tid & 31;
        const int mat  = w >> 2;                 // 0: left, 1: right
        const int kq   = w & 3,  k0 = kq * 16;
        const float* bias = mat ? br : bl;
        const float* rsrc = (mat ? Rb : Lb) + dg0 + 2 * lane;   // 8B-aligned pairs
        const ulonglong2* wt2 = reinterpret_cast<const ulonglong2*>(sm + OFF_C + mat * WT_SZ);

        u64 acc[8][2];
        #pragma unroll
        for (int kp = 0; kp < 8; ++kp) {
            u64 bp_ = pk2(__ldg(bias + k0 + 2 * kp), __ldg(bias + k0 + 2 * kp + 1));
            acc[kp][0] = bp_; acc[kp][1] = bp_;
        }
        #pragma unroll 4
        for (int l = 0; l < 64; ++l) {
            float2 rv = __ldg(reinterpret_cast<const float2*>(rsrc + l * 1024));
            u64 p0 = pk2(rv.x, rv.x), p1 = pk2(rv.y, rv.y);
            const ulonglong2* wl_ = wt2 + l * 17 + 4 * kq;
            #pragma unroll
            for (int i = 0; i < 4; ++i) {
                ulonglong2 ww = wl_[i];          // broadcast LDS.128 = 2 k-pairs
                fma2(acc[2 * i][0],     ww.x, p0);
                fma2(acc[2 * i][1],     ww.x, p1);
                fma2(acc[2 * i + 1][0], ww.y, p0);
                fma2(acc[2 * i + 1][1], ww.y, p1);
            }
        }
        // thread owns tile cols (2lane+1, 2lane+2)
        float* ost = sm + (mat ? (OFF_B + 8 * ST) : OFF_A) + 2 * lane + 1;
        #pragma unroll
        for (int kp = 0; kp < 8; ++kp) {
            float a0, b0_, a1, b1_;
            upk2(acc[kp][0], a0, b0_);           // col 2lane+1: k even, k odd
            upk2(acc[kp][1], a1, b1_);           // col 2lane+2
            ost[(k0 + 2 * kp) * ST + 0]     = a0;
            ost[(k0 + 2 * kp) * ST + 1]     = a1;
            ost[(k0 + 2 * kp + 1) * ST + 0] = b0_;
            ost[(k0 + 2 * kp + 1) * ST + 1] = b1_;
        }

        // tail cols (0,65) via H scratch: 2 mats x 64 k x 2 l-halves
        const int hmat = tid >> 7;
        const int hk   = (tid >> 1) & 63;
        const int lh   = tid & 1;
        const u64* Hp = reinterpret_cast<const u64*>(sm) + U64_H + hmat * 64;
        const float* wt = sm + OFF_C + hmat * WT_SZ + hk;
        const float* bias2 = hmat ? br : bl;
        u64 hacc = lh ? 0ull : pk2(__ldg(bias2 + hk), __ldg(bias2 + hk));
        #pragma unroll 8
        for (int t = 0; t < 32; ++t) {
            int l = 32 * lh + t;
            float wv = wt[l * ST];
            fma2(hacc, pk2(wv, wv), Hp[l]);      // lo: col0, hi: col65
        }
        float alo, ahi; upk2(hacc, alo, ahi);
        alo += __shfl_xor_sync(0xFFFFFFFFu, alo, 1);
        ahi += __shfl_xor_sync(0xFFFFFFFFu, ahi, 1);
        if (!lh) {
            float* tb = sm + (hmat ? (OFF_B + 8 * ST) : OFF_A) + hk * ST;
            tb[0]  = alo;
            tb[65] = ahi;
        }
    }
    __syncthreads();

    // ---- phase 2: correlation, triangular paired blocks ----
    {
        const int cp = tid & 31;                  // col pair (2cp, 2cp+1)
        const int ig = tid >> 5;                  // 0..7
        const u64* ap = reinterpret_cast<const u64*>(sm) + cp;           // row j at j*34
        const u64* bp = reinterpret_cast<const u64*>(sm) + U64_B + cp;   // orig row X at (X-56)*34
        u64* cst = reinterpret_cast<u64*>(sm) + U64_C + cp;
        const u64 keep = (dg0 == 0 && cp == 0) ? 0xFFFFFFFF00000000ull : ~0ull;

        #pragma unroll 1
        for (int blk = 0; blk < 2; ++blk) {
            const int i0  = blk ? (64 + 8 * ig) : (8 * ig);
            const int jlo = blk ? (8 * ig) : 0;
            const int nch = blk ? (8 - ig) : (ig + 1);
            u64 acc[8], win[8];
            #pragma unroll
            for (int q = 0; q < 8; ++q) acc[q] = 0ull;
            #pragma unroll
            for (int q = 1; q < 8; ++q) win[q] = bp[(jlo + 71 - i0 - q) * 34];
            #pragma unroll 1
            for (int ch = 0; ch < nch; ++ch) {
                const int j0 = jlo + ch * 8;
                u64 a2[8];
                #pragma unroll
                for (int t = 0; t < 8; ++t) a2[t] = ap[(j0 + t) * 34];
                #pragma unroll
                for (int t = 0; t < 8; ++t) {
                    u64 nv = bp[(j0 + t + 71 - i0) * 34];
                    fma2(acc[0], a2[t], nv);
                    #pragma unroll
                    for (int q = 1; q < 8; ++q) fma2(acc[q], a2[t], win[q]);
                    #pragma unroll
                    for (int q = 7; q > 1; --q) win[q] = win[q - 1];
                    win[1] = nv;
                }
            }
            #pragma unroll
            for (int q = 0; q < 8; ++q) cst[(i0 + q) * 34] = acc[q] & keep;
        }

        // tail cols (64,65): windowed j-range, stride-2 split per thread pair
        const int hi = tid >> 1;
        const int jh = tid & 1;
        const int jlo = (hi > 63) ? (hi - 63) : 0;
        const int jhi = (hi < 63) ? hi : 63;
        const u64* a2p = reinterpret_cast<const u64*>(sm) + 32;          // A halo word
        const u64* b2p = reinterpret_cast<const u64*>(sm) + U64_B + 32;  // B halo word
        u64 hacc = 0ull;
        #pragma unroll 4
        for (int j = jlo + jh; j <= jhi; j += 2)
            fma2(hacc, a2p[j * 34], b2p[(j + 71 - hi) * 34]);            // local rows 8..71
        float alo, ahi; upk2(hacc, alo, ahi);
        alo += __shfl_xor_sync(0xFFFFFFFFu, alo, 1);
        ahi += __shfl_xor_sync(0xFFFFFFFFu, ahi, 1);
        if (!jh) {
            u64 v = pk2(alo, ahi);
            if (dg0 == 960) v &= 0x00000000FFFFFFFFull;   // col 65 = d 1024 invalid
            reinterpret_cast<u64*>(sm)[U64_C + hi * 34 + 32] = v;
        }
    }

    // ---- phase 3: conv(128->64,k=3), 4d x 4k, weights staged in quarters over A+B ----
    const int dq = tid & 15, kq = tid >> 4;
    const int d0 = 4 * dq;
    u64 acc3[2][4];
    #pragma unroll
    for (int p = 0; p < 2; ++p)
        #pragma unroll
        for (int dd = 0; dd < 4; ++dd) acc3[p][dd] = 0ull;

    ulonglong2* wAs = reinterpret_cast<ulonglong2*>(sm);        // A region (dead)
    u64*        wBs = reinterpret_cast<u64*>(sm) + U64_B;       // B region (dead)
    #pragma unroll 1
    for (int s = 0; s < 4; ++s) {
        __syncthreads();   // corr written (s=0) / prev-stage weight reads done
        for (int i = tid; i < 1024; i += 256) {
            int kp = i >> 5, cl = i & 31;
            const float* s0 = Wconv + (2 * kp) * 384 + (32 * s + cl) * 3;
            ulonglong2 v;
            v.x = pk2(__ldg(s0 + 0), __ldg(s0 + 384));
            v.y = pk2(__ldg(s0 + 1), __ldg(s0 + 385));
            wAs[kp * 33 + cl] = v;
            wBs[kp * 33 + cl] = pk2(__ldg(s0 + 2), __ldg(s0 + 386));
        }
        __syncthreads();
        const float* cb = sm + OFF_C + (32 * s) * ST + d0;
        #pragma unroll 4
        for (int cl = 0; cl < 32; ++cl) {
            const float* crow = cb + cl * ST;
            ulonglong2 cA = *reinterpret_cast<const ulonglong2*>(crow);  // d0..d0+3
            float2     cC = *reinterpret_cast<const float2*>(crow + 4);  // d0+4, d0+5
            float f0, f1, f2, f3;
            upk2(cA.x, f0, f1); upk2(cA.y, f2, f3);
            u64 cv[6] = { pk2(f0, f0), pk2(f1, f1), pk2(f2, f2),
                          pk2(f3, f3), pk2(cC.x, cC.x), pk2(cC.y, cC.y) };
            #pragma unroll
            for (int p = 0; p < 2; ++p) {
                ulonglong2 wa = wAs[(2 * kq + p) * 33 + cl];
                u64        wb = wBs[(2 * kq + p) * 33 + cl];
                #pragma unroll
                for (int dd = 0; dd < 4; ++dd) {
                    fma2(acc3[p][dd], wa.x, cv[dd]);
                    fma2(acc3[p][dd], wa.y, cv[dd + 1]);
                    fma2(acc3[p][dd], wb,   cv[dd + 2]);
                }
            }
        }
    }

    float* ob = out + (size_t)b * 65536 + dg0 + d0;
    #pragma unroll
    for (int p = 0; p < 2; ++p) {
        float lo[4], hi[4];
        #pragma unroll
        for (int dd = 0; dd < 4; ++dd) upk2(acc3[p][dd], lo[dd], hi[dd]);
        float* o0 = ob + (size_t)(4 * kq + 2 * p) * Dc;
        *reinterpret_cast<float4*>(o0)      = make_float4(lo[0], lo[1], lo[2], lo[3]);
        *reinterpret_cast<float4*>(o0 + Dc) = make_float4(hi[0], hi[1], hi[2], hi[3]);
    }
}

extern "C" void kernel_launch(void* const* d_in, const int* in_sizes, int n_in,
                              void* d_out, int out_size)
{
    (void)in_sizes; (void)n_in; (void)out_size;
    const float* left  = (const float*)d_in[0];
    const float* right = (const float*)d_in[1];
    const float* Wl    = (const float*)d_in[2];
    const float* bl    = (const float*)d_in[3];
    const float* Wr    = (const float*)d_in[4];
    const float* br    = (const float*)d_in[5];
    const float* Wconv = (const float*)d_in[6];
    float* out = (float*)d_out;

    cudaFuncSetAttribute(cc_fused_kernel,
                         cudaFuncAttributeMaxDynamicSharedMemorySize, SMEM_BYTES);
    dim3 grid(Dc / 64, 256, 1);   // 4096 CTAs: one batch x 64-wide d-tile
    cc_fused_kernel<<<grid, 256, SMEM_BYTES>>>(left, right, Wl, bl, Wr, br, Wconv, out);
}